// round 16
// baseline (speedup 1.0000x reference)
#include <cuda_runtime.h>
#include <cuda_bf16.h>
#include <cstdint>
#include <cstddef>

#define B_  2
#define S_  2048
#define D_  1024
#define H_  16
#define DH_ 64
#define M_  (B_ * S_)
#define SP1 (S_ + 1)

typedef __nv_bfloat16 bf16;

static constexpr size_t NMD = (size_t)M_ * D_;
static constexpr size_t NDD = (size_t)D_ * D_;
static constexpr size_t NSS = (size_t)B_ * H_ * S_ * S_;

__device__ __align__(4096) bf16 g_Ah[4 * NMD];
__device__ __align__(4096) bf16 g_Al[4 * NMD];
__device__ __align__(4096) bf16 g_Wh[5 * NDD];
__device__ __align__(4096) bf16 g_Wl[5 * NDD];
__device__ __align__(4096) bf16 g_qhu_h[NMD], g_qhu_l[NMD];
__device__ __align__(4096) bf16 g_qhv_h[NMD], g_qhv_l[NMD];
__device__ __align__(4096) bf16 g_kh_h[NMD],  g_kh_l[NMD];
__device__ __align__(4096) bf16 g_ph_h[NMD],  g_ph_l[NMD];
__device__ __align__(4096) bf16 g_vT_h[NMD],  g_vT_l[NMD];
__device__ __align__(4096) float g_scores[NSS];
__device__ __align__(4096) bf16 g_ao_h[NMD], g_ao_l[NMD];

__device__ __forceinline__ uint32_t smem_u32(const void* p) {
    uint32_t a;
    asm("{ .reg .u64 t; cvta.to.shared.u64 t, %1; cvt.u32.u64 %0, t; }" : "=r"(a) : "l"(p));
    return a;
}
__device__ __forceinline__ void ldsm4(uint32_t* r, uint32_t addr) {
    asm volatile("ldmatrix.sync.aligned.m8n8.x4.shared.b16 {%0,%1,%2,%3}, [%4];"
                 : "=r"(r[0]), "=r"(r[1]), "=r"(r[2]), "=r"(r[3]) : "r"(addr));
}
__device__ __forceinline__ void mma16816(float* c, const uint32_t* a, const uint32_t* b) {
    asm volatile(
        "mma.sync.aligned.m16n8k16.row.col.f32.bf16.bf16.f32 "
        "{%0,%1,%2,%3}, {%4,%5,%6,%7}, {%8,%9}, {%0,%1,%2,%3};"
        : "+f"(c[0]), "+f"(c[1]), "+f"(c[2]), "+f"(c[3])
        : "r"(a[0]), "r"(a[1]), "r"(a[2]), "r"(a[3]), "r"(b[0]), "r"(b[1]));
}
#define CP16(dst, src) \
    asm volatile("cp.async.ca.shared.global [%0], [%1], 16;" :: "r"(dst), "l"(src))
#define CPCOMMIT() asm volatile("cp.async.commit_group;" ::: "memory")
#define CPWAIT1()  asm volatile("cp.async.wait_group 1;" ::: "memory")
#define CPWAIT0()  asm volatile("cp.async.wait_group 0;" ::: "memory")

#define EPI_VT    2
#define EPI_SCORE 3
#define EPI_SHIFT 4
#define EPI_OUT   6
#define EPI_PROJ  7

// C[m,n] = sum_k A[m,k]*B[n,k]; A,B hi+lo bf16; NP passes (1:AhBh 2:+AhBl 3:+AlBh).
// Block 128 x BN, 8 warps (2M x 4N), BK=32, 2-stage cp.async pipeline.
template<int BN, int EPI, int NP>
__global__ __launch_bounds__(256) void wmma_gemm(
    const bf16* __restrict__ Ah, const bf16* __restrict__ Al,
    const bf16* __restrict__ Bh, const bf16* __restrict__ Bl,
    int Kdim, int lda, int ldb,
    float* __restrict__ outF,
    bf16* __restrict__ o1h, bf16* __restrict__ o1l,
    const float* __restrict__ b1, const float* __restrict__ b2,
    const float* __restrict__ b3, const float* __restrict__ b4)
{
    constexpr int STR = 40;
    constexpr int WN  = BN / 4;
    constexpr int NI  = WN / 8;
    constexpr int NB  = BN / 64;
    constexpr int SA  = 128 * STR * 2;
    constexpr int SAL = (NP >= 3) ? SA : 0;
    constexpr int SB  = BN * STR * 2;
    constexpr int SS  = SA + SAL + 2 * SB;

    extern __shared__ char sm[];

    const int tid = threadIdx.x, wid = tid >> 5, lane = tid & 31;
    const int wm = wid & 1, wn = wid >> 1;
    const int z = blockIdx.z;
    const int bm = blockIdx.y * 128, bn = blockIdx.x * BN;

    const bf16 *Ahp = Ah, *Alp = Al, *Bhp = Bh, *Blp = Bl;
    if (EPI == EPI_PROJ) {
        int sel = (z == 0) ? 0 : ((z == 1) ? 1 : 3);
        Ahp = g_Ah + (size_t)sel * NMD; Alp = g_Al + (size_t)sel * NMD;
        Bhp = g_Wh + (size_t)sel * NDD; Blp = g_Wl + (size_t)sel * NDD;
    }

    size_t aoff = 0, boff = 0;
    if (EPI == EPI_SCORE || EPI == EPI_SHIFT) {
        aoff = (size_t)(z >> 4) * ((size_t)S_ * D_) + (size_t)(z & 15) * DH_;
        boff = aoff;
    }

    float acc[4][NI][4];
#pragma unroll
    for (int i = 0; i < 4; i++)
#pragma unroll
        for (int j = 0; j < NI; j++)
#pragma unroll
            for (int c = 0; c < 4; c++) acc[i][j][c] = 0.f;

    const int nch = Kdim / 32;

    auto issue = [&](int i, int st) {
        const int k0 = i * 32;
        char* base = sm + st * SS;
        const uint32_t uA   = smem_u32(base);
        const uint32_t uAl2 = uA + SA;
        const uint32_t uB   = uA + SA + SAL;
        const uint32_t uBl2 = uB + SB;
#pragma unroll
        for (int j = 0; j < 2; j++) {
            int idx = tid + j * 256;
            int r = idx >> 2, c4 = idx & 3;
            uint32_t doff = (uint32_t)(r * (STR * 2) + c4 * 16);
            CP16(uA + doff, Ahp + aoff + (size_t)(bm + r) * lda + k0 + c4 * 8);
            if (NP >= 3)
                CP16(uAl2 + doff, Alp + aoff + (size_t)(bm + r) * lda + k0 + c4 * 8);
        }
#pragma unroll
        for (int j = 0; j < NB; j++) {
            int idx = tid + j * 256;
            int r = idx >> 2, c4 = idx & 3;
            uint32_t doff = (uint32_t)(r * (STR * 2) + c4 * 16);
            CP16(uB + doff,   Bhp + boff + (size_t)(bn + r) * ldb + k0 + c4 * 8);
            CP16(uBl2 + doff, Blp + boff + (size_t)(bn + r) * ldb + k0 + c4 * 8);
        }
        CPCOMMIT();
    };

    issue(0, 0);

    for (int i = 0; i < nch; i++) {
        if (i + 1 < nch) { issue(i + 1, (i + 1) & 1); CPWAIT1(); }
        else             { CPWAIT0(); }
        __syncthreads();

        char* base = sm + (i & 1) * SS;
        const uint32_t uAh = smem_u32(base);
        const uint32_t uAl = uAh + SA;
        const uint32_t uBh = uAh + SA + SAL;
        const uint32_t uBl = uBh + SB;

#pragma unroll
        for (int ks = 0; ks < 32; ks += 16) {
            uint32_t bhf[NI][2], blf[NI][2];
#pragma unroll
            for (int p = 0; p < NI / 2; p++) {
                int g = lane >> 3;
                int row = wn * WN + p * 16 + (lane & 7) + ((g >> 1) << 3);
                int colb = ks * 2 + (g & 1) * 16;
                uint32_t off = (uint32_t)(row * (STR * 2) + colb);
                uint32_t r4[4];
                ldsm4(r4, uBh + off);
                bhf[2 * p][0] = r4[0]; bhf[2 * p][1] = r4[1];
                bhf[2 * p + 1][0] = r4[2]; bhf[2 * p + 1][1] = r4[3];
                ldsm4(r4, uBl + off);
                blf[2 * p][0] = r4[0]; blf[2 * p][1] = r4[1];
                blf[2 * p + 1][0] = r4[2]; blf[2 * p + 1][1] = r4[3];
            }
#pragma unroll
            for (int mi = 0; mi < 4; mi++) {
                int arow = wm * 64 + mi * 16 + (lane & 15);
                int acolb = ks * 2 + (lane >> 4) * 16;
                uint32_t aob = (uint32_t)(arow * (STR * 2) + acolb);
                uint32_t ah4[4], al4[4];
                ldsm4(ah4, uAh + aob);
                if (NP >= 3) ldsm4(al4, uAl + aob);
#pragma unroll
                for (int ni = 0; ni < NI; ni++) {
                    mma16816(acc[mi][ni], ah4, bhf[ni]);
                    if (NP >= 2) mma16816(acc[mi][ni], ah4, blf[ni]);
                    if (NP >= 3) mma16816(acc[mi][ni], al4, bhf[ni]);
                }
            }
        }
        __syncthreads();
    }

    // ---- epilogue ----
#pragma unroll
    for (int mi = 0; mi < 4; mi++) {
#pragma unroll
        for (int ni = 0; ni < NI; ni++) {
#pragma unroll
            for (int c = 0; c < 4; c++) {
                int m = bm + wm * 64 + mi * 16 + (lane >> 2) + ((c >> 1) << 3);
                int n = bn + wn * WN + ni * 8 + ((lane & 3) << 1) + (c & 1);
                float v = acc[mi][ni][c];

                if constexpr (EPI == EPI_PROJ) {
                    size_t o = (size_t)m * D_ + n;
                    if (z == 0) {
                        float vv = v + b1[n];
                        float x1 = vv + b2[n], x2 = vv + b3[n];
                        bf16 h1 = __float2bfloat16(x1);
                        g_qhu_h[o] = h1;
                        g_qhu_l[o] = __float2bfloat16(x1 - __bfloat162float(h1));
                        bf16 h2 = __float2bfloat16(x2);
                        g_qhv_h[o] = h2;
                        g_qhv_l[o] = __float2bfloat16(x2 - __bfloat162float(h2));
                    } else if (z == 1) {
                        float vv = v + b4[n];
                        bf16 h = __float2bfloat16(vv);
                        g_kh_h[o] = h;
                        g_kh_l[o] = __float2bfloat16(vv - __bfloat162float(h));
                    } else {
                        bf16 h = __float2bfloat16(v);
                        g_ph_h[o] = h;
                        g_ph_l[o] = __float2bfloat16(v - __bfloat162float(h));
                    }
                } else if constexpr (EPI == EPI_VT) {
                    float vv = v + b1[n];
                    int b = m >> 11, s = m & (S_ - 1);
                    int h = n >> 6, d = n & 63;
                    size_t o = ((size_t)((b * H_ + h) * DH_ + d)) * S_ + s;
                    bf16 hh = __float2bfloat16(vv);
                    o1h[o] = hh; o1l[o] = __float2bfloat16(vv - __bfloat162float(hh));
                } else if constexpr (EPI == EPI_SCORE) {
                    outF[(size_t)z * S_ * S_ + (size_t)m * S_ + n] = v;
                } else if constexpr (EPI == EPI_SHIFT) {
                    int flat = m * SP1 + n + 1;
                    int qo = (flat >> 11) - 1;
                    int ko = flat & (S_ - 1);
                    if (qo >= 0) {
                        size_t o = (size_t)z * S_ * S_ + (size_t)qo * S_ + ko;
                        outF[o] += v;
                    }
                } else {  // EPI_OUT
                    outF[(size_t)m * D_ + n] = v + b1[n];
                }
            }
        }
    }
}

// ---------------------------------------------------------------------------
// PAV: fused online-softmax + attn@V. Grid (16 qtiles, 32 z). 256 thr, 8 warps.
// Streams score k-tiles (fp32), keeps probs in smem only (hi/lo bf16), 3-pass AV.
// ---------------------------------------------------------------------------
#define PAV_SS   (128 * 132 * 4)     // 67584  score fp32, stride 132 floats
#define PAV_SP   (128 * 136 * 2)     // 34816  prob bf16, stride 136
#define PAV_SV   (64 * 136 * 2)      // 17408  V bf16, stride 136
#define PAV_SMEM (PAV_SS + 2 * PAV_SP + 2 * PAV_SV + 5 * 512)

__global__ __launch_bounds__(256) void pav_kernel(
    const float* __restrict__ scores, const bf16* __restrict__ vTh,
    const bf16* __restrict__ vTl, bf16* __restrict__ aoh, bf16* __restrict__ aol)
{
    extern __shared__ char sm[];
    float* sS  = (float*)sm;
    bf16*  sPh = (bf16*)(sm + PAV_SS);
    bf16*  sPl = (bf16*)(sm + PAV_SS + PAV_SP);
    bf16*  sVh = (bf16*)(sm + PAV_SS + 2 * PAV_SP);
    bf16*  sVl = (bf16*)(sm + PAV_SS + 2 * PAV_SP + PAV_SV);
    float* mrow  = (float*)(sm + PAV_SS + 2 * PAV_SP + 2 * PAV_SV);
    float* lrow  = mrow + 128;
    float* frow  = mrow + 256;
    float* tmaxs = mrow + 384;
    float* psums = mrow + 512;

    const int tid = threadIdx.x, wid = tid >> 5, lane = tid & 31;
    const int wm = wid & 1, wn = wid >> 1;
    const int z = blockIdx.y;
    const int bm = blockIdx.x * 128;
    const size_t zoff = (size_t)z * S_ * S_;
    const size_t voff = (size_t)z * DH_ * S_;

    const uint32_t uS  = smem_u32(sS);
    const uint32_t uPh = smem_u32(sPh);
    const uint32_t uPl = smem_u32(sPl);
    const uint32_t uVh = smem_u32(sVh);
    const uint32_t uVl = smem_u32(sVl);

    float acc[4][2][4];
#pragma unroll
    for (int i = 0; i < 4; i++)
#pragma unroll
        for (int j = 0; j < 2; j++)
#pragma unroll
            for (int c = 0; c < 4; c++) acc[i][j][c] = 0.f;

    if (tid < 128) { mrow[tid] = -1e30f; lrow[tid] = 0.f; }
    __syncthreads();

    const int r = tid >> 1;
    const int bcol = (tid & 1) * 64;

    for (int kt = 0; kt < 16; kt++) {
        const int k0 = kt * 128;
        // load score tile (128x128 fp32) + V tiles (64x128 bf16 hi/lo)
#pragma unroll
        for (int j = 0; j < 16; j++) {
            int idx = tid + j * 256;
            int rr = idx >> 5, cc = idx & 31;
            CP16(uS + rr * 528 + cc * 16,
                 scores + zoff + (size_t)(bm + rr) * S_ + k0 + cc * 4);
        }
#pragma unroll
        for (int j = 0; j < 4; j++) {
            int idx = tid + j * 256;
            int rr = idx >> 4, cc = idx & 15;
            CP16(uVh + rr * 272 + cc * 16, vTh + voff + (size_t)rr * S_ + k0 + cc * 8);
            CP16(uVl + rr * 272 + cc * 16, vTl + voff + (size_t)rr * S_ + k0 + cc * 8);
        }
        CPCOMMIT(); CPWAIT0();
        __syncthreads();

        // tile row max
        float tmax = -1e30f;
#pragma unroll
        for (int c = 0; c < 64; c++)
            tmax = fmaxf(tmax, sS[r * 132 + bcol + c]);
        tmax = fmaxf(tmax, __shfl_xor_sync(0xffffffffu, tmax, 1));
        if ((tid & 1) == 0) tmaxs[r] = tmax * 0.03125f;
        __syncthreads();
        if (tid < 128) {
            float mo = mrow[tid];
            float mn = fmaxf(mo, tmaxs[tid]);
            frow[tid] = __expf(mo - mn);
            mrow[tid] = mn;
        }
        __syncthreads();

        // exp + prob hi/lo to smem + row sums; rescale acc
        {
            float mn = mrow[r];
            float sum = 0.f;
#pragma unroll
            for (int c = 0; c < 64; c += 2) {
                float p0 = __expf(sS[r * 132 + bcol + c]     * 0.03125f - mn);
                float p1 = __expf(sS[r * 132 + bcol + c + 1] * 0.03125f - mn);
                sum += p0 + p1;
                bf16 h0 = __float2bfloat16(p0), h1 = __float2bfloat16(p1);
                __nv_bfloat162 th; th.x = h0; th.y = h1;
                *(__nv_bfloat162*)(sPh + r * 136 + bcol + c) = th;
                __nv_bfloat162 tl;
                tl.x = __float2bfloat16(p0 - __bfloat162float(h0));
                tl.y = __float2bfloat16(p1 - __bfloat162float(h1));
                *(__nv_bfloat162*)(sPl + r * 136 + bcol + c) = tl;
            }
            sum += __shfl_xor_sync(0xffffffffu, sum, 1);
            if ((tid & 1) == 0) psums[r] = sum;
        }
#pragma unroll
        for (int mi = 0; mi < 4; mi++) {
#pragma unroll
            for (int c4 = 0; c4 < 4; c4++) {
                int row = wm * 64 + mi * 16 + (lane >> 2) + ((c4 >> 1) << 3);
                float f = frow[row];
                acc[mi][0][c4] *= f;
                acc[mi][1][c4] *= f;
            }
        }
        __syncthreads();
        if (tid < 128) lrow[tid] = lrow[tid] * frow[tid] + psums[tid];

        // mma: 3-pass (Ph*Vh, Ph*Vl, Pl*Vh) over 128-k tile
#pragma unroll
        for (int ks = 0; ks < 128; ks += 16) {
            uint32_t bhf[2][2], blf[2][2];
            {
                int g = lane >> 3;
                int row = wn * 16 + (lane & 7) + ((g >> 1) << 3);
                int colb = ks * 2 + (g & 1) * 16;
                uint32_t off = (uint32_t)(row * 272 + colb);
                uint32_t r4[4];
                ldsm4(r4, uVh + off);
                bhf[0][0] = r4[0]; bhf[0][1] = r4[1];
                bhf[1][0] = r4[2]; bhf[1][1] = r4[3];
                ldsm4(r4, uVl + off);
                blf[0][0] = r4[0]; blf[0][1] = r4[1];
                blf[1][0] = r4[2]; blf[1][1] = r4[3];
            }
#pragma unroll
            for (int mi = 0; mi < 4; mi++) {
                int arow = wm * 64 + mi * 16 + (lane & 15);
                int acolb = ks * 2 + (lane >> 4) * 16;
                uint32_t aob = (uint32_t)(arow * 272 + acolb);
                uint32_t ah4[4], al4[4];
                ldsm4(ah4, uPh + aob);
                ldsm4(al4, uPl + aob);
#pragma unroll
                for (int ni = 0; ni < 2; ni++) {
                    mma16816(acc[mi][ni], ah4, bhf[ni]);
                    mma16816(acc[mi][ni], ah4, blf[ni]);
                    mma16816(acc[mi][ni], al4, bhf[ni]);
                }
            }
        }
        __syncthreads();
    }

    // normalize + write attention output (head-interleaved) hi/lo
    const int b = z >> 4, h = z & 15;
#pragma unroll
    for (int mi = 0; mi < 4; mi++) {
#pragma unroll
        for (int ni = 0; ni < 2; ni++) {
#pragma unroll
            for (int c = 0; c < 4; c++) {
                int ml = wm * 64 + mi * 16 + (lane >> 2) + ((c >> 1) << 3);
                int n  = wn * 16 + ni * 8 + ((lane & 3) << 1) + (c & 1);
                float v = acc[mi][ni][c] / lrow[ml];
                size_t o = ((size_t)(b * S_ + bm + ml)) * D_ + h * DH_ + n;
                bf16 hh = __float2bfloat16(v);
                aoh[o] = hh;
                aol[o] = __float2bfloat16(v - __bfloat162float(hh));
            }
        }
    }
}

struct Ptr5 { const float* p[5]; };

__global__ __launch_bounds__(256) void conv_multi(
    Ptr5 in, bf16* __restrict__ hi, bf16* __restrict__ lo, size_t perN, int n4)
{
    int i = blockIdx.x * 256 + threadIdx.x;
    if (i >= n4) return;
    int w = blockIdx.y;
    const float* src = in.p[w];
    bf16* h = hi + (size_t)w * perN;
    bf16* l = lo + (size_t)w * perN;
    float4 v = ((const float4*)src)[i];
    bf16 h0 = __float2bfloat16(v.x), h1 = __float2bfloat16(v.y);
    bf16 h2 = __float2bfloat16(v.z), h3 = __float2bfloat16(v.w);
    h[i * 4 + 0] = h0; h[i * 4 + 1] = h1; h[i * 4 + 2] = h2; h[i * 4 + 3] = h3;
    l[i * 4 + 0] = __float2bfloat16(v.x - __bfloat162float(h0));
    l[i * 4 + 1] = __float2bfloat16(v.y - __bfloat162float(h1));
    l[i * 4 + 2] = __float2bfloat16(v.z - __bfloat162float(h2));
    l[i * 4 + 3] = __float2bfloat16(v.w - __bfloat162float(h3));
}

extern "C" void kernel_launch(void* const* d_in, const int* in_sizes, int n_in,
                              void* d_out, int out_size)
{
    const float* q   = (const float*)d_in[0];
    const float* k   = (const float*)d_in[1];
    const float* v   = (const float*)d_in[2];
    const float* pe  = (const float*)d_in[3];
    const float* Wq  = (const float*)d_in[4];
    const float* bq  = (const float*)d_in[5];
    const float* Wk  = (const float*)d_in[6];
    const float* bk  = (const float*)d_in[7];
    const float* Wv  = (const float*)d_in[8];
    const float* bv  = (const float*)d_in[9];
    const float* Wp  = (const float*)d_in[10];
    const float* ub  = (const float*)d_in[11];
    const float* vb  = (const float*)d_in[12];
    const float* Wo  = (const float*)d_in[13];
    const float* bo  = (const float*)d_in[14];
    float* out = (float*)d_out;

    bf16 *Ah, *Al, *Wh, *Wl, *qhu_h, *qhu_l, *qhv_h, *qhv_l, *kh_h, *kh_l;
    bf16 *ph_h, *ph_l, *vT_h, *vT_l, *ao_h, *ao_l;
    float *scores;
    cudaGetSymbolAddress((void**)&Ah, g_Ah);
    cudaGetSymbolAddress((void**)&Al, g_Al);
    cudaGetSymbolAddress((void**)&Wh, g_Wh);
    cudaGetSymbolAddress((void**)&Wl, g_Wl);
    cudaGetSymbolAddress((void**)&qhu_h, g_qhu_h);
    cudaGetSymbolAddress((void**)&qhu_l, g_qhu_l);
    cudaGetSymbolAddress((void**)&qhv_h, g_qhv_h);
    cudaGetSymbolAddress((void**)&qhv_l, g_qhv_l);
    cudaGetSymbolAddress((void**)&kh_h, g_kh_h);
    cudaGetSymbolAddress((void**)&kh_l, g_kh_l);
    cudaGetSymbolAddress((void**)&ph_h, g_ph_h);
    cudaGetSymbolAddress((void**)&ph_l, g_ph_l);
    cudaGetSymbolAddress((void**)&vT_h, g_vT_h);
    cudaGetSymbolAddress((void**)&vT_l, g_vT_l);
    cudaGetSymbolAddress((void**)&scores, g_scores);
    cudaGetSymbolAddress((void**)&ao_h, g_ao_h);
    cudaGetSymbolAddress((void**)&ao_l, g_ao_l);

    const int DS_P2_128 = 2 * (10240 + 2 * 10240);           // 61440
    const int DS_P3_128 = 2 * (2 * 10240 + 2 * 10240);       // 81920
    cudaFuncSetAttribute(wmma_gemm<128, EPI_PROJ, 2>,  cudaFuncAttributeMaxDynamicSharedMemorySize, DS_P2_128);
    cudaFuncSetAttribute(wmma_gemm<128, EPI_VT, 3>,    cudaFuncAttributeMaxDynamicSharedMemorySize, DS_P3_128);
    cudaFuncSetAttribute(wmma_gemm<128, EPI_SCORE, 2>, cudaFuncAttributeMaxDynamicSharedMemorySize, DS_P2_128);
    cudaFuncSetAttribute(wmma_gemm<128, EPI_SHIFT, 2>, cudaFuncAttributeMaxDynamicSharedMemorySize, DS_P2_128);
    cudaFuncSetAttribute(wmma_gemm<128, EPI_OUT, 3>,   cudaFuncAttributeMaxDynamicSharedMemorySize, DS_P3_128);
    cudaFuncSetAttribute(pav_kernel,                   cudaFuncAttributeMaxDynamicSharedMemorySize, PAV_SMEM);

    const int nMD4 = (int)(NMD / 4), nDD4 = (int)(NDD / 4);
    Ptr5 pin;  pin.p[0] = q;  pin.p[1] = k;  pin.p[2] = v;  pin.p[3] = pe; pin.p[4] = nullptr;
    Ptr5 pw;   pw.p[0] = Wq; pw.p[1] = Wk; pw.p[2] = Wv; pw.p[3] = Wp; pw.p[4] = Wo;
    conv_multi<<<dim3(nMD4 / 256, 4), 256>>>(pin, Ah, Al, NMD, nMD4);
    conv_multi<<<dim3(nDD4 / 256, 5), 256>>>(pw,  Wh, Wl, NDD, nDD4);

    // 1) merged Q/K/P projections (z: 0=QUV, 1=K, 2=P) + separate V-transpose
    dim3 gp3(D_ / 128, M_ / 128, 3);
    wmma_gemm<128, EPI_PROJ, 2><<<gp3, 256, DS_P2_128>>>(
        nullptr, nullptr, nullptr, nullptr, D_, D_, D_,
        nullptr, nullptr, nullptr, bq, ub, vb, bk);
    dim3 gp(D_ / 128, M_ / 128, 1);
    wmma_gemm<128, EPI_VT, 3><<<gp, 256, DS_P3_128>>>(
        Ah + 2 * NMD, Al + 2 * NMD, Wh + 2 * NDD, Wl + 2 * NDD, D_, D_, D_,
        nullptr, vT_h, vT_l, bv, nullptr, nullptr, nullptr);

    // 2) content scores; pos scores with fused rel-shift scatter-add
    dim3 gs(S_ / 128, S_ / 128, B_ * H_);
    wmma_gemm<128, EPI_SCORE, 2><<<gs, 256, DS_P2_128>>>(
        qhu_h, qhu_l, kh_h, kh_l, DH_, D_, D_,
        scores, nullptr, nullptr, nullptr, nullptr, nullptr, nullptr);
    wmma_gemm<128, EPI_SHIFT, 2><<<gs, 256, DS_P2_128>>>(
        qhv_h, qhv_l, ph_h, ph_l, DH_, D_, D_,
        scores, nullptr, nullptr, nullptr, nullptr, nullptr, nullptr);

    // 3) fused online softmax + attn@V
    pav_kernel<<<dim3(S_ / 128, B_ * H_), 256, PAV_SMEM>>>(
        scores, vT_h, vT_l, ao_h, ao_l);

    // 4) output projection
    wmma_gemm<128, EPI_OUT, 3><<<gp, 256, DS_P3_128>>>(
        ao_h, ao_l, Wh + 4 * NDD, Wl + 4 * NDD, D_, D_, D_,
        out, nullptr, nullptr, bo, nullptr, nullptr, nullptr);
}